// round 6
// baseline (speedup 1.0000x reference)
#include <cuda_runtime.h>
#include <math.h>

#define BSZ 8
#define LSEQ 512
#define DM 256
#define NH 8
#define DH 32
#define DS 30

#define TQ 16      // q rows per CTA
#define TQW 8      // q rows per warp
#define TK 32
#define NKT (LSEQ / TK)
#define NTHREADS 512

// strides (floats)
#define KS_STRIDE 260   // 16B-aligned rows, conflict-free float4 phases
#define VS_STRIDE 260
#define ST_K 36         // per-k stride in ST (s padded 30->36, pads zero)
#define ST_Q 1156       // per-q stride in ST (32*36 + 4 pad)
#define P_STRIDE 33
#define SC_STRIDE 36

// ---- dynamic shared memory layout (float offsets) ----
#define OFF_QS 0                  // [8][16][32]   = 4096
#define OFF_QW 4096               // [8][16][32]   = 4096 (qwsk padded 30->32 zeros)
#define OFF_KS 8192               // [32][260]     = 8320
#define OFF_VS 16512              // [32][260]     = 8320
#define OFF_P  24832              // [8][16][33]   = 4224
#define OFF_SC 29056              // [8][16][36]   = 4608
#define OFF_ST 33664              // [16]*1156     = 18496
#define OFF_LS 52160              // [16][8]       = 128
#define SMEM_FLOATS 52288
#define SMEM_BYTES (SMEM_FLOATS * 4)

// 24 MB scratch: qh, kh, vh, ctx (each 8*512*256) + scores0 (8*512*512)
__device__ float g_scratch[4 * BSZ * LSEQ * DM + BSZ * LSEQ * LSEQ];
__device__ int g_mask_is_byte;

// ---------------------------------------------------------------------------
__global__ void detect_mask_kernel(const unsigned char* __restrict__ m, int nbytes)
{
    __shared__ int any;
    if (threadIdx.x == 0) any = 0;
    __syncthreads();
    int local = 0;
    for (int i = threadIdx.x; i < nbytes; i += blockDim.x)
        if ((i & 3) != 0 && m[i] != 0) local = 1;
    if (local) atomicOr(&any, 1);
    __syncthreads();
    if (threadIdx.x == 0) g_mask_is_byte = any;
}

// ---------------------------------------------------------------------------
// SGEMM body (64x64 tile, 256 threads, 4x4 per thread)
// ---------------------------------------------------------------------------
__device__ __forceinline__ void sgemm_body(
    const float* __restrict__ A, const float* __restrict__ W,
    const float* __restrict__ bias, float* __restrict__ C, float scale,
    int m0, int n0)
{
    __shared__ float As[64 * 17];
    __shared__ float Bs[16 * 64];

    const int tid = threadIdx.x;
    const int tx = tid & 15, ty = tid >> 4;

    float acc[4][4] = {};

    for (int k0 = 0; k0 < 256; k0 += 16) {
#pragma unroll
        for (int j = 0; j < 4; j++) {
            int e = tid + j * 256;
            int m = e >> 4, kk = e & 15;
            As[m * 17 + kk] = A[(size_t)(m0 + m) * 256 + k0 + kk];
        }
#pragma unroll
        for (int j = 0; j < 4; j++) {
            int e = tid + j * 256;
            int kk = e >> 6, n = e & 63;
            Bs[kk * 64 + n] = W[(size_t)(k0 + kk) * 256 + n0 + n];
        }
        __syncthreads();
#pragma unroll
        for (int kk = 0; kk < 16; kk++) {
            float a0 = As[(ty * 4 + 0) * 17 + kk];
            float a1 = As[(ty * 4 + 1) * 17 + kk];
            float a2 = As[(ty * 4 + 2) * 17 + kk];
            float a3 = As[(ty * 4 + 3) * 17 + kk];
            float4 bv = *reinterpret_cast<const float4*>(&Bs[kk * 64 + tx * 4]);
            acc[0][0] += a0 * bv.x; acc[0][1] += a0 * bv.y; acc[0][2] += a0 * bv.z; acc[0][3] += a0 * bv.w;
            acc[1][0] += a1 * bv.x; acc[1][1] += a1 * bv.y; acc[1][2] += a1 * bv.z; acc[1][3] += a1 * bv.w;
            acc[2][0] += a2 * bv.x; acc[2][1] += a2 * bv.y; acc[2][2] += a2 * bv.z; acc[2][3] += a2 * bv.w;
            acc[3][0] += a3 * bv.x; acc[3][1] += a3 * bv.y; acc[3][2] += a3 * bv.z; acc[3][3] += a3 * bv.w;
        }
        __syncthreads();
    }

#pragma unroll
    for (int i = 0; i < 4; i++)
#pragma unroll
        for (int j = 0; j < 4; j++) {
            int m = m0 + ty * 4 + i, n = n0 + tx * 4 + j;
            C[(size_t)m * 256 + n] = (acc[i][j] + bias[n]) * scale;
        }
}

__global__ void __launch_bounds__(256) sgemm256(
    const float* __restrict__ A, const float* __restrict__ W,
    const float* __restrict__ bias, float* __restrict__ C, float scale)
{
    sgemm_body(A, W, bias, C, scale, blockIdx.y * 64, blockIdx.x * 64);
}

__global__ void __launch_bounds__(256) qkv_gemm(
    const float* __restrict__ Aq, const float* __restrict__ Ak, const float* __restrict__ Av,
    const float* __restrict__ Wq, const float* __restrict__ Wk, const float* __restrict__ Wv,
    const float* __restrict__ bq, const float* __restrict__ bk, const float* __restrict__ bv,
    float* __restrict__ Cq, float* __restrict__ Ck, float* __restrict__ Cv)
{
    const float *A, *W, *bias; float* C; float scale;
    if (blockIdx.z == 0)      { A = Aq; W = Wq; bias = bq; C = Cq; scale = 0.17677669529663688f; }
    else if (blockIdx.z == 1) { A = Ak; W = Wk; bias = bk; C = Ck; scale = 1.0f; }
    else                      { A = Av; W = Wv; bias = bv; C = Cv; scale = 1.0f; }
    sgemm_body(A, W, bias, C, scale, blockIdx.y * 64, blockIdx.x * 64);
}

// ---------------------------------------------------------------------------
// Fused attention, fixed-max softmax. Vectorized layouts:
//   ST [q][k][36] (q-stride 1156, s-pads zero): float4 everywhere.
//   Score phase: warp=(head, q-half), lane=k.
//   Accumulate phase: lane=(q-in-group, oct); acc owns d-oct, ps owns s-oct;
//   p read from P smem (broadcast, feeds 16 FMAs) — no shuffles.
// ---------------------------------------------------------------------------
__global__ void __launch_bounds__(NTHREADS, 1) attn_kernel(
    const float* __restrict__ qh, const float* __restrict__ kh, const float* __restrict__ vh,
    const float* __restrict__ st_g, const void* __restrict__ kmask_raw,
    const float* __restrict__ wsk, const float* __restrict__ wsv, const float* __restrict__ bsv,
    float* __restrict__ ctx, float* __restrict__ scores0)
{
    extern __shared__ float sm[];
    float* QS = sm + OFF_QS;
    float* QW = sm + OFF_QW;
    float* KS = sm + OFF_KS;
    float* VS = sm + OFF_VS;
    float* P  = sm + OFF_P;
    float* SC = sm + OFF_SC;
    float* ST = sm + OFF_ST;
    float* LS = sm + OFF_LS;

    const int tid = threadIdx.x;
    const int w = tid >> 5, lane = tid & 31;
    const int h = w & 7, qgp = w >> 3;          // head, q-half
    const int b = blockIdx.x >> 5;
    const int q0 = (blockIdx.x & 31) * TQ;
    const int mask_is_byte = g_mask_is_byte;
    const unsigned char* km8 = (const unsigned char*)kmask_raw;
    const int* km32 = (const int*)kmask_raw;

    // accumulate-phase lane identity
    const int qhat = qgp * TQW + (lane >> 2);   // CTA q index owned in accumulate
    const int oct  = lane & 3;                  // 8-wide d-oct / s-oct

    // staging identity: warp <-> q row, lane <-> k
    const int sqq = w;
    const int sk = lane;
    const size_t st_row_base = ((size_t)b * LSEQ + q0 + sqq) * LSEQ + sk;

    // ---- load Q tile -> QS[h][q][32]; wsk -> SC temp; zero QW, ST ----
    {
        const float4* qg4 = reinterpret_cast<const float4*>(qh + ((size_t)b * LSEQ + q0) * DM);
        for (int f = tid; f < TQ * DM / 4; f += NTHREADS) {
            int q = f >> 6, c4 = f & 63;
            float4 v = qg4[f];
            int hh = c4 >> 3, d = (c4 & 7) * 4;
            float* dst = &QS[(hh * TQ + q) * 32 + d];
            dst[0] = v.x; dst[1] = v.y; dst[2] = v.z; dst[3] = v.w;
        }
    }
    for (int i = tid; i < DS * DH; i += NTHREADS) SC[i] = wsk[i];
    for (int i = tid; i < NH * TQ * 32; i += NTHREADS) QW[i] = 0.f;
    for (int i = tid; i < TQ * ST_Q; i += NTHREADS) ST[i] = 0.f;
    __syncthreads();

    // qwsk[h,q,s] = sum_d QS[h,q,d] * wsk[s,d]
    for (int i = tid; i < NH * TQ * DS; i += NTHREADS) {
        int hh = i / (TQ * DS);
        int r = i - hh * (TQ * DS);
        int q = r / DS;
        int s = r - q * DS;
        const float* qp = &QS[(hh * TQ + q) * 32];
        const float* wp = &SC[s * 32];
        float a = 0.f;
#pragma unroll
        for (int d = 0; d < 32; d++) a += qp[d] * wp[d];
        QW[(hh * TQ + q) * 32 + s] = a;
    }

    // ---- initial staging: ST tile 0 (regs) + KV tile 0 ----
    float2 pre[15];
    {
        const float2* src = reinterpret_cast<const float2*>(st_g + st_row_base * DS);
#pragma unroll
        for (int i = 0; i < 15; i++) pre[i] = src[i];
    }
    {
        const float4* kg4 = reinterpret_cast<const float4*>(kh + ((size_t)b * LSEQ) * DM);
        const float4* vg4 = reinterpret_cast<const float4*>(vh + ((size_t)b * LSEQ) * DM);
#pragma unroll
        for (int j = 0; j < 4; j++) {
            int idx = tid + j * NTHREADS;
            int kk = idx >> 6, c = (idx & 63) * 4;
            float4 kv = kg4[idx];
            float* kd = &KS[kk * KS_STRIDE + c];
            kd[0] = kv.x; kd[1] = kv.y; kd[2] = kv.z; kd[3] = kv.w;
            float4 vv = vg4[idx];
            float* vd = &VS[kk * VS_STRIDE + c];
            vd[0] = vv.x; vd[1] = vv.y; vd[2] = vv.z; vd[3] = vv.w;
        }
    }
    {
        float2* dst = reinterpret_cast<float2*>(&ST[sqq * ST_Q + sk * ST_K]);
#pragma unroll
        for (int i = 0; i < 15; i++) dst[i] = pre[i];
    }
    __syncthreads();

    float acc[8], ps[8], lsum[TQW];
#pragma unroll
    for (int i = 0; i < 8; i++) { acc[i] = 0.f; ps[i] = 0.f; }
#pragma unroll
    for (int q = 0; q < TQW; q++) lsum[q] = 0.f;

    for (int kt = 0; kt < NKT; kt++) {
        const int k0 = kt * TK;

        // prefetch next struct tile into registers
        if (kt + 1 < NKT) {
            const float2* src = reinterpret_cast<const float2*>(st_g + (st_row_base + k0 + TK) * DS);
#pragma unroll
            for (int i = 0; i < 15; i++) pre[i] = src[i];
        }

        const int midx = b * LSEQ + k0 + lane;
        const bool masked = mask_is_byte ? (km8[midx] != 0) : (km32[midx] != 0);

        // K row for this lane's k (vectorized)
        float kreg[32];
        {
            const float4* kp = reinterpret_cast<const float4*>(&KS[lane * KS_STRIDE + h * 32]);
#pragma unroll
            for (int d4 = 0; d4 < 8; d4++) {
                float4 kv = kp[d4];
                kreg[d4 * 4] = kv.x; kreg[d4 * 4 + 1] = kv.y;
                kreg[d4 * 4 + 2] = kv.z; kreg[d4 * 4 + 3] = kv.w;
            }
        }

        // ---- score phase: lane = k ----
#pragma unroll
        for (int q = 0; q < TQW; q++) {
            const int qq = qgp * TQW + q;
            const float4* qv = reinterpret_cast<const float4*>(&QS[(h * TQ + qq) * 32]);
            float s = 0.f;
#pragma unroll
            for (int d4 = 0; d4 < 8; d4++) {
                float4 qd = qv[d4];
                s += qd.x * kreg[d4 * 4] + qd.y * kreg[d4 * 4 + 1]
                   + qd.z * kreg[d4 * 4 + 2] + qd.w * kreg[d4 * 4 + 3];
            }
            const float4* qwv = reinterpret_cast<const float4*>(&QW[(h * TQ + qq) * 32]);
            const float4* stp = reinterpret_cast<const float4*>(&ST[qq * ST_Q + lane * ST_K]);
#pragma unroll
            for (int s4 = 0; s4 < 8; s4++) {       // s 30..35 pads are zero (QW too)
                float4 ww = qwv[s4];
                float4 sv = stp[s4];
                s += ww.x * sv.x + ww.y * sv.y + ww.z * sv.z + ww.w * sv.w;
            }
            if (masked) s = -1e30f;
            float p = __expf(s);
            lsum[q] += p;
            P[(h * TQ + qq) * P_STRIDE + lane] = p;
            if (h == 0)
                scores0[((size_t)(b * LSEQ + q0 + qq)) * LSEQ + k0 + lane] = p;
        }
        __syncwarp();

        // ---- accumulate phase: lane = (qhat, oct) ----
        {
            const float* prow = &P[(h * TQ + qhat) * P_STRIDE];
            const float* vrow = &VS[h * 32 + oct * 8];
            const float* strow = &ST[qhat * ST_Q + oct * 8];
#pragma unroll 8
            for (int k = 0; k < TK; k++) {
                float p = prow[k];
                float4 v0 = *reinterpret_cast<const float4*>(&vrow[k * VS_STRIDE]);
                float4 v1 = *reinterpret_cast<const float4*>(&vrow[k * VS_STRIDE + 4]);
                float4 s0 = *reinterpret_cast<const float4*>(&strow[k * ST_K]);
                float4 s1 = *reinterpret_cast<const float4*>(&strow[k * ST_K + 4]);
                acc[0] += p * v0.x; acc[1] += p * v0.y; acc[2] += p * v0.z; acc[3] += p * v0.w;
                acc[4] += p * v1.x; acc[5] += p * v1.y; acc[6] += p * v1.z; acc[7] += p * v1.w;
                ps[0] += p * s0.x; ps[1] += p * s0.y; ps[2] += p * s0.z; ps[3] += p * s0.w;
                ps[4] += p * s1.x; ps[5] += p * s1.y; ps[6] += p * s1.z; ps[7] += p * s1.w;
            }
        }

        __syncthreads();
        // commit prefetched ST + stage next KV
        if (kt + 1 < NKT) {
            {
                float2* dst = reinterpret_cast<float2*>(&ST[sqq * ST_Q + sk * ST_K]);
#pragma unroll
                for (int i = 0; i < 15; i++) dst[i] = pre[i];
            }
            const float4* kg4 = reinterpret_cast<const float4*>(kh + ((size_t)b * LSEQ + k0 + TK) * DM);
            const float4* vg4 = reinterpret_cast<const float4*>(vh + ((size_t)b * LSEQ + k0 + TK) * DM);
#pragma unroll
            for (int j = 0; j < 4; j++) {
                int idx = tid + j * NTHREADS;
                int kk = idx >> 6, c = (idx & 63) * 4;
                float4 kv = kg4[idx];
                float* kd = &KS[kk * KS_STRIDE + c];
                kd[0] = kv.x; kd[1] = kv.y; kd[2] = kv.z; kd[3] = kv.w;
                float4 vv = vg4[idx];
                float* vd = &VS[kk * VS_STRIDE + c];
                vd[0] = vv.x; vd[1] = vv.y; vd[2] = vv.z; vd[3] = vv.w;
            }
            __syncthreads();
        }
    }

    // ---- epilogue ----
    __syncthreads();   // all tiles done; safe to reuse QS region for wsv

    // stage wsv into QS region
    float* WS = QS;
    for (int i = tid; i < DS * DH; i += NTHREADS) WS[i] = wsv[i];

    // reduce lsum across lanes; store per-warp row sums
#pragma unroll
    for (int q = 0; q < TQW; q++) {
        float l = lsum[q];
#pragma unroll
        for (int off = 16; off; off >>= 1)
            l += __shfl_xor_sync(0xffffffffu, l, off);
        lsum[q] = l;
    }
    if (lane == 0) {
#pragma unroll
        for (int q = 0; q < TQW; q++) LS[w * TQW + q] = lsum[q];
    }

    // stage ps into SC: lane (qhat, oct) owns s = oct*8 + ss
#pragma unroll
    for (int ss = 0; ss < 8; ss++)
        SC[(h * TQ + qhat) * SC_STRIDE + oct * 8 + ss] = ps[ss];
    __syncthreads();

    // ctx[qhat, h*32 + oct*8 + dd] = (acc + ps_row @ wsv) / l + bsv
    {
        float inv = 1.f / LS[w * TQW + (lane >> 2)];
        const float* scrow = &SC[(h * TQ + qhat) * SC_STRIDE];
        float c[8];
#pragma unroll
        for (int dd = 0; dd < 8; dd++) c[dd] = acc[dd];
#pragma unroll
        for (int s = 0; s < DS; s++) {
            float pv = scrow[s];
            const float* wrow = &WS[s * 32 + oct * 8];
#pragma unroll
            for (int dd = 0; dd < 8; dd++) c[dd] += pv * wrow[dd];
        }
        float* outp = &ctx[((size_t)(b * LSEQ + q0 + qhat)) * DM + h * 32 + oct * 8];
#pragma unroll
        for (int dd = 0; dd < 8; dd++) c[dd] = c[dd] * inv + bsv[oct * 8 + dd];
        float4 o0 = { c[0], c[1], c[2], c[3] };
        float4 o1 = { c[4], c[5], c[6], c[7] };
        reinterpret_cast<float4*>(outp)[0] = o0;
        reinterpret_cast<float4*>(outp)[1] = o1;
    }
}

// ---------------------------------------------------------------------------
// Normalize rows of unnormalized p (fin_attn): out = p / sum(p).
// ---------------------------------------------------------------------------
__global__ void __launch_bounds__(256) normalize_rows(
    const float* __restrict__ P, float* __restrict__ O)
{
    const int row = blockIdx.x;
    const float* s = P + (size_t)row * LSEQ;
    float* o = O + (size_t)row * LSEQ;
    const int t = threadIdx.x;

    float a = s[t], b = s[t + 256];
    float sum = a + b;
    __shared__ float red[8];
#pragma unroll
    for (int off = 16; off; off >>= 1) sum += __shfl_xor_sync(0xffffffffu, sum, off);
    if ((t & 31) == 0) red[t >> 5] = sum;
    __syncthreads();
    float sAll = 0.f;
#pragma unroll
    for (int i = 0; i < 8; i++) sAll += red[i];
    float inv = 1.f / sAll;
    o[t] = a * inv;
    o[t + 256] = b * inv;
}

// ---------------------------------------------------------------------------
extern "C" void kernel_launch(void* const* d_in, const int* in_sizes, int n_in,
                              void* d_out, int out_size)
{
    const float* key   = (const float*)d_in[0];
    const float* value = (const float*)d_in[1];
    const float* query = (const float*)d_in[2];

    // Inputs 3/4: disambiguate structure vs k_pad_mask by element count.
    const float* structure;
    const void*  kmaskp;
    if (in_sizes[3] == BSZ * LSEQ) {
        kmaskp    = d_in[3];
        structure = (const float*)d_in[4];
    } else {
        structure = (const float*)d_in[3];
        kmaskp    = d_in[4];
    }

    const float* wq  = (const float*)d_in[5];
    const float* bq  = (const float*)d_in[6];
    const float* wk  = (const float*)d_in[7];
    const float* bk  = (const float*)d_in[8];
    const float* wv  = (const float*)d_in[9];
    const float* bv  = (const float*)d_in[10];
    const float* wsk = (const float*)d_in[11];
    // d_in[12] = bsk: softmax-invariant, dropped.
    const float* wsv = (const float*)d_in[13];
    const float* bsv = (const float*)d_in[14];
    const float* wf  = (const float*)d_in[15];
    const float* bf  = (const float*)d_in[16];

    float* out = (float*)d_out;
    float* fin = out + (size_t)BSZ * LSEQ * DM;

    float* scratch = nullptr;
    cudaGetSymbolAddress((void**)&scratch, g_scratch);
    float* qh  = scratch;
    float* kh  = qh + (size_t)BSZ * LSEQ * DM;
    float* vh  = kh + (size_t)BSZ * LSEQ * DM;
    float* ctx = vh + (size_t)BSZ * LSEQ * DM;
    float* sc0 = ctx + (size_t)BSZ * LSEQ * DM;

    detect_mask_kernel<<<1, 256>>>((const unsigned char*)kmaskp, BSZ * LSEQ);

    qkv_gemm<<<dim3(4, 64, 3), 256>>>(query, key, value,
                                      wq, wk, wv, bq, bk, bv,
                                      qh, kh, vh);

    cudaFuncSetAttribute(attn_kernel, cudaFuncAttributeMaxDynamicSharedMemorySize, SMEM_BYTES);
    attn_kernel<<<BSZ * (LSEQ / TQ), NTHREADS, SMEM_BYTES>>>(
        qh, kh, vh, structure, kmaskp, wsk, wsv, bsv, ctx, sc0);

    normalize_rows<<<BSZ * LSEQ, 256>>>(sc0, fin);
    sgemm256<<<dim3(4, 64), 256>>>(ctx, wf, bf, out, 1.0f);
}

// round 8
// speedup vs baseline: 1.0889x; 1.0889x over previous
#include <cuda_runtime.h>
#include <math.h>

#define BSZ 8
#define LSEQ 512
#define DM 256
#define NH 8
#define DH 32
#define DS 30

#define TQ 16      // q rows per CTA
#define TQW 8      // q rows per warp
#define TK 32
#define NKT (LSEQ / TK)
#define NTHREADS 512

// ---- dynamic shared memory layout for attn (float offsets) ----
#define OFF_QS 0                 // [8][16][32]  = 4096
#define OFF_QW 4096              // [8][16][32]  = 4096 (qwsk padded 30->32 with zeros)
#define OFF_KS 8192              // [32][257]    = 8224
#define OFF_VS 16416             // [32][257]    = 8224
#define OFF_SC 24640             // [8][16][36]  = 4608
#define OFF_ST 29248             // [16][32][31] = 15872 (+32 pad)
#define SMEM_FLOATS (29248 + 15872 + 32)
#define SMEM_BYTES (SMEM_FLOATS * 4)

// 24 MB scratch: qh, kh, vh, ctx (each 8*512*256) + scores0 (8*512*512)
__device__ float g_scratch[4 * BSZ * LSEQ * DM + BSZ * LSEQ * LSEQ];
__device__ int g_mask_is_byte;

// ---------------------------------------------------------------------------
__global__ void detect_mask_kernel(const unsigned char* __restrict__ m, int nbytes)
{
    __shared__ int any;
    if (threadIdx.x == 0) any = 0;
    __syncthreads();
    int local = 0;
    for (int i = threadIdx.x; i < nbytes; i += blockDim.x)
        if ((i & 3) != 0 && m[i] != 0) local = 1;
    if (local) atomicOr(&any, 1);
    __syncthreads();
    if (threadIdx.x == 0) g_mask_is_byte = any;
}

// tiny dummy to shift ncu's captured launch index onto attn_kernel
__global__ void dummy_kernel()
{
    if (threadIdx.x == 0) g_scratch[0] = g_scratch[0];
}

// ---------------------------------------------------------------------------
// Fast SGEMM: C[M,256] = (A[M,256] @ W[256,256] + bias) * scale
// 128x128 tile, 256 threads, 8x8 microtile, double-buffered smem.
// ---------------------------------------------------------------------------
__device__ __forceinline__ void gemm128_body(
    const float* __restrict__ A, const float* __restrict__ W,
    const float* __restrict__ bias, float* __restrict__ C, float scale,
    int m0, int n0)
{
    __shared__ float As[2][8][128];
    __shared__ float Bs[2][8][128];

    const int tid = threadIdx.x;
    const int am = tid >> 1;             // 0..127
    const int ak = (tid & 1) * 4;        // 0 or 4
    const int br = tid >> 5;             // 0..7
    const int bc = (tid & 31) * 4;       // 0..124
    const int tx = tid & 15, ty = tid >> 4;

    float4 av = *reinterpret_cast<const float4*>(&A[(size_t)(m0 + am) * 256 + ak]);
    float4 bv = *reinterpret_cast<const float4*>(&W[(size_t)br * 256 + n0 + bc]);

    As[0][ak + 0][am] = av.x; As[0][ak + 1][am] = av.y;
    As[0][ak + 2][am] = av.z; As[0][ak + 3][am] = av.w;
    *reinterpret_cast<float4*>(&Bs[0][br][bc]) = bv;
    __syncthreads();

    float acc[8][8] = {};
    int buf = 0;

    for (int k0 = 0; k0 < 256; k0 += 8) {
        const bool more = (k0 + 8 < 256);
        if (more) {
            av = *reinterpret_cast<const float4*>(&A[(size_t)(m0 + am) * 256 + k0 + 8 + ak]);
            bv = *reinterpret_cast<const float4*>(&W[(size_t)(k0 + 8 + br) * 256 + n0 + bc]);
        }
#pragma unroll
        for (int kk = 0; kk < 8; kk++) {
            float a[8], b[8];
            *reinterpret_cast<float4*>(&a[0]) = *reinterpret_cast<const float4*>(&As[buf][kk][ty * 8]);
            *reinterpret_cast<float4*>(&a[4]) = *reinterpret_cast<const float4*>(&As[buf][kk][ty * 8 + 4]);
            *reinterpret_cast<float4*>(&b[0]) = *reinterpret_cast<const float4*>(&Bs[buf][kk][tx * 8]);
            *reinterpret_cast<float4*>(&b[4]) = *reinterpret_cast<const float4*>(&Bs[buf][kk][tx * 8 + 4]);
#pragma unroll
            for (int i = 0; i < 8; i++)
#pragma unroll
                for (int j = 0; j < 8; j++) acc[i][j] += a[i] * b[j];
        }
        if (more) {
            buf ^= 1;
            As[buf][ak + 0][am] = av.x; As[buf][ak + 1][am] = av.y;
            As[buf][ak + 2][am] = av.z; As[buf][ak + 3][am] = av.w;
            *reinterpret_cast<float4*>(&Bs[buf][br][bc]) = bv;
            __syncthreads();
        }
    }

    float bb[8];
#pragma unroll
    for (int j = 0; j < 8; j++) bb[j] = bias[n0 + tx * 8 + j];
#pragma unroll
    for (int i = 0; i < 8; i++) {
        float4 c0, c1;
        c0.x = (acc[i][0] + bb[0]) * scale; c0.y = (acc[i][1] + bb[1]) * scale;
        c0.z = (acc[i][2] + bb[2]) * scale; c0.w = (acc[i][3] + bb[3]) * scale;
        c1.x = (acc[i][4] + bb[4]) * scale; c1.y = (acc[i][5] + bb[5]) * scale;
        c1.z = (acc[i][6] + bb[6]) * scale; c1.w = (acc[i][7] + bb[7]) * scale;
        float* cp = &C[(size_t)(m0 + ty * 8 + i) * 256 + n0 + tx * 8];
        reinterpret_cast<float4*>(cp)[0] = c0;
        reinterpret_cast<float4*>(cp)[1] = c1;
    }
}

__global__ void __launch_bounds__(256) gemm128(
    const float* __restrict__ A, const float* __restrict__ W,
    const float* __restrict__ bias, float* __restrict__ C, float scale)
{
    gemm128_body(A, W, bias, C, scale, blockIdx.y * 128, blockIdx.x * 128);
}

__global__ void __launch_bounds__(256) qkv_gemm(
    const float* __restrict__ Aq, const float* __restrict__ Ak, const float* __restrict__ Av,
    const float* __restrict__ Wq, const float* __restrict__ Wk, const float* __restrict__ Wv,
    const float* __restrict__ bq, const float* __restrict__ bk, const float* __restrict__ bv,
    float* __restrict__ Cq, float* __restrict__ Ck, float* __restrict__ Cv)
{
    const float *A, *W, *bias; float* C; float scale;
    if (blockIdx.z == 0)      { A = Aq; W = Wq; bias = bq; C = Cq; scale = 0.17677669529663688f; }
    else if (blockIdx.z == 1) { A = Ak; W = Wk; bias = bk; C = Ck; scale = 1.0f; }
    else                      { A = Av; W = Wv; bias = bv; C = Cv; scale = 1.0f; }
    gemm128_body(A, W, bias, C, scale, blockIdx.y * 128, blockIdx.x * 128);
}

// ---------------------------------------------------------------------------
// Fused attention, fixed-max softmax (scores provably small, shift 0 exact).
// Struct staging is COALESCED: a warp's (q-row, 32 k) slice is 3840 contiguous
// bytes; lanes read float2 linearly (nL=2/LDG), then scatter to ST[k*31+s]
// via an incremental (k,s) walk.
// ---------------------------------------------------------------------------
__global__ void __launch_bounds__(NTHREADS, 1) attn_kernel(
    const float* __restrict__ qh, const float* __restrict__ kh, const float* __restrict__ vh,
    const float* __restrict__ st_g, const void* __restrict__ kmask_raw,
    const float* __restrict__ wsk, const float* __restrict__ wsv, const float* __restrict__ bsv,
    float* __restrict__ ctx, float* __restrict__ scores0)
{
    extern __shared__ float sm[];
    float* QS = sm + OFF_QS;
    float* QW = sm + OFF_QW;
    float* KS = sm + OFF_KS;
    float* VS = sm + OFF_VS;
    float* SC = sm + OFF_SC;
    float* ST = sm + OFF_ST;

    const int tid = threadIdx.x;
    const int w = tid >> 5, lane = tid & 31;
    const int h = w & 7, qgp = w >> 3;          // head, q-half
    const int b = blockIdx.x >> 5;
    const int q0 = (blockIdx.x & 31) * TQ;
    const int mask_is_byte = g_mask_is_byte;
    const unsigned char* km8 = (const unsigned char*)kmask_raw;
    const int* km32 = (const int*)kmask_raw;

    // staging identity: warp <-> q row (contiguous 960-float slice per tile)
    const int sqq = w;
    const float* st_qrow = st_g + (((size_t)b * LSEQ + q0 + sqq) * LSEQ) * DS;
    float* st_dst = &ST[sqq * 32 * 31];
    // starting (k,s) for this lane's linear elements e = lane*2 (+64 per step)
    const int ek0 = (lane * 2) / DS;
    const int es0 = (lane * 2) % DS;

    // ---- load Q tile [16][256] -> QS[h][q][32] ----
    {
        const float4* qg4 = reinterpret_cast<const float4*>(qh + ((size_t)b * LSEQ + q0) * DM);
        for (int f = tid; f < TQ * DM / 4; f += NTHREADS) {
            int q = f >> 6, c4 = f & 63;
            float4 v = qg4[f];
            int hh = c4 >> 3, d = (c4 & 7) * 4;
            float* dst = &QS[(hh * TQ + q) * 32 + d];
            dst[0] = v.x; dst[1] = v.y; dst[2] = v.z; dst[3] = v.w;
        }
    }
    for (int i = tid; i < DS * DH; i += NTHREADS) SC[i] = wsk[i];
    for (int i = tid; i < NH * TQ * 32; i += NTHREADS) QW[i] = 0.f;
    __syncthreads();

    // qwsk[h,q,s] = sum_d QS[h,q,d] * wsk[s,d]
    for (int i = tid; i < NH * TQ * DS; i += NTHREADS) {
        int hh = i / (TQ * DS);
        int r = i - hh * (TQ * DS);
        int q = r / DS;
        int s = r - q * DS;
        const float* qp = &QS[(hh * TQ + q) * 32];
        const float* wp = &SC[s * 32];
        float a = 0.f;
#pragma unroll
        for (int d = 0; d < 32; d++) a += qp[d] * wp[d];
        QW[(hh * TQ + q) * 32 + s] = a;
    }

    // ---- initial staging: ST tile 0 (coalesced) + KV tile 0 ----
    float2 pre[15];
    {
        const float2* src = reinterpret_cast<const float2*>(st_qrow);
#pragma unroll
        for (int i = 0; i < 15; i++) pre[i] = src[i * 32 + lane];
    }
    {
        const float4* kg4 = reinterpret_cast<const float4*>(kh + ((size_t)b * LSEQ) * DM);
        const float4* vg4 = reinterpret_cast<const float4*>(vh + ((size_t)b * LSEQ) * DM);
#pragma unroll
        for (int j = 0; j < 4; j++) {
            int idx = tid + j * NTHREADS;
            int kk = idx >> 6, c = (idx & 63) * 4;
            float4 kv = kg4[idx];
            float* kd = &KS[kk * 257 + c];
            kd[0] = kv.x; kd[1] = kv.y; kd[2] = kv.z; kd[3] = kv.w;
            float4 vv = vg4[idx];
            float* vd = &VS[kk * 257 + c];
            vd[0] = vv.x; vd[1] = vv.y; vd[2] = vv.z; vd[3] = vv.w;
        }
    }
    {
        int kk = ek0, ss = es0;
#pragma unroll
        for (int i = 0; i < 15; i++) {
            st_dst[kk * 31 + ss] = pre[i].x;
            int k2 = kk, s2 = ss + 1;
            if (s2 == DS) { s2 = 0; k2++; }
            st_dst[k2 * 31 + s2] = pre[i].y;
            ss += 4; kk += 2;                 // advance e by 64: 64 = 2*30 + 4
            if (ss >= DS) { ss -= DS; kk++; }
        }
    }
    __syncthreads();

    float acc[TQW], ps[TQW], lsum[TQW];
#pragma unroll
    for (int q = 0; q < TQW; q++) { acc[q] = 0.f; ps[q] = 0.f; lsum[q] = 0.f; }

    for (int kt = 0; kt < NKT; kt++) {
        const int k0 = kt * TK;

        // coalesced prefetch of next struct slice
        if (kt + 1 < NKT) {
            const float2* src = reinterpret_cast<const float2*>(st_qrow + (size_t)(k0 + TK) * DS);
#pragma unroll
            for (int i = 0; i < 15; i++) pre[i] = src[i * 32 + lane];
        }

        const int midx = b * LSEQ + k0 + lane;
        const bool masked = mask_is_byte ? (km8[midx] != 0) : (km32[midx] != 0);

        // K row for this lane's k
        float kreg[32];
        {
            const float* kp = &KS[lane * 257 + h * 32];
#pragma unroll
            for (int d = 0; d < 32; d++) kreg[d] = kp[d];
        }

        float preg[TQW];
#pragma unroll
        for (int q = 0; q < TQW; q++) {
            const int qq = qgp * TQW + q;
            const float4* qv = reinterpret_cast<const float4*>(&QS[(h * TQ + qq) * 32]);
            float s = 0.f;
#pragma unroll
            for (int d4 = 0; d4 < 8; d4++) {
                float4 qd = qv[d4];
                s += qd.x * kreg[d4 * 4] + qd.y * kreg[d4 * 4 + 1]
                   + qd.z * kreg[d4 * 4 + 2] + qd.w * kreg[d4 * 4 + 3];
            }
            const float4* qwv = reinterpret_cast<const float4*>(&QW[(h * TQ + qq) * 32]);
            const float* stp = &ST[(qq * 32 + lane) * 31];
#pragma unroll
            for (int s4 = 0; s4 < 7; s4++) {
                float4 ww = qwv[s4];
                s += ww.x * stp[s4 * 4] + ww.y * stp[s4 * 4 + 1]
                   + ww.z * stp[s4 * 4 + 2] + ww.w * stp[s4 * 4 + 3];
            }
            s += QW[(h * TQ + qq) * 32 + 28] * stp[28] + QW[(h * TQ + qq) * 32 + 29] * stp[29];
            if (masked) s = -1e30f;

            float p = __expf(s);
            preg[q] = p;
            lsum[q] += p;
            if (h == 0)
                scores0[((size_t)(b * LSEQ + q0 + qq)) * LSEQ + k0 + lane] = p;
        }

        // ---- accumulate: acc[q] += p*v[d=lane], ps[q] += p*struct[s=lane] ----
        const float* vsp = &VS[h * 32 + lane];
#pragma unroll 4
        for (int k = 0; k < TK; k++) {
            float vv = vsp[k * 257];
            const float* stk = &ST[k * 31 + lane];
#pragma unroll
            for (int q = 0; q < TQW; q++) {
                float p = __shfl_sync(0xffffffffu, preg[q], k);
                acc[q] += p * vv;
                ps[q]  += p * stk[(qgp * TQW + q) * 992];
            }
        }

        __syncthreads();
        // commit prefetched ST + stage next KV
        if (kt + 1 < NKT) {
            {
                int kk = ek0, ss = es0;
#pragma unroll
                for (int i = 0; i < 15; i++) {
                    st_dst[kk * 31 + ss] = pre[i].x;
                    int k2 = kk, s2 = ss + 1;
                    if (s2 == DS) { s2 = 0; k2++; }
                    st_dst[k2 * 31 + s2] = pre[i].y;
                    ss += 4; kk += 2;
                    if (ss >= DS) { ss -= DS; kk++; }
                }
            }
            const float4* kg4 = reinterpret_cast<const float4*>(kh + ((size_t)b * LSEQ + k0 + TK) * DM);
            const float4* vg4 = reinterpret_cast<const float4*>(vh + ((size_t)b * LSEQ + k0 + TK) * DM);
#pragma unroll
            for (int j = 0; j < 4; j++) {
                int idx = tid + j * NTHREADS;
                int kk = idx >> 6, c = (idx & 63) * 4;
                float4 kv = kg4[idx];
                float* kd = &KS[kk * 257 + c];
                kd[0] = kv.x; kd[1] = kv.y; kd[2] = kv.z; kd[3] = kv.w;
                float4 vv = vg4[idx];
                float* vd = &VS[kk * 257 + c];
                vd[0] = vv.x; vd[1] = vv.y; vd[2] = vv.z; vd[3] = vv.w;
            }
            __syncthreads();
        }
    }

    // ---- final row-sum reduction ----
#pragma unroll
    for (int q = 0; q < TQW; q++) {
        float l = lsum[q];
#pragma unroll
        for (int off = 16; off; off >>= 1)
            l += __shfl_xor_sync(0xffffffffu, l, off);
        lsum[q] = l;
    }

    // ---- epilogue: ctx = (acc + ps@wsv)/l + bsv ----
    __syncthreads();
    for (int i = tid; i < DS * DH; i += NTHREADS) ST[i] = wsv[i];
#pragma unroll
    for (int q = 0; q < TQW; q++)
        if (lane < DS) SC[(h * TQ + qgp * TQW + q) * 36 + lane] = ps[q];
    __syncthreads();

    const float bsvv = bsv[lane];
#pragma unroll
    for (int q = 0; q < TQW; q++) {
        const int qq = qgp * TQW + q;
        float inv = 1.f / lsum[q];
        float c = acc[q];
        const float* pr = &SC[(h * TQ + qq) * 36];
#pragma unroll
        for (int s = 0; s < DS; s++) c += pr[s] * ST[s * 32 + lane];
        ctx[((size_t)(b * LSEQ + q0 + qq)) * DM + h * 32 + lane] = c * inv + bsvv;
    }
}

// ---------------------------------------------------------------------------
// Normalize rows of unnormalized p (fin_attn): out = p / sum(p).
// ---------------------------------------------------------------------------
__global__ void __launch_bounds__(256) normalize_rows(
    const float* __restrict__ P, float* __restrict__ O)
{
    const int row = blockIdx.x;
    const float* s = P + (size_t)row * LSEQ;
    float* o = O + (size_t)row * LSEQ;
    const int t = threadIdx.x;

    float a = s[t], b = s[t + 256];
    float sum = a + b;
    __shared__ float red[8];
#pragma unroll
    for (int off = 16; off; off >>= 1) sum += __shfl_xor_sync(0xffffffffu, sum, off);
    if ((t & 31) == 0) red[t >> 5] = sum;
    __syncthreads();
    float sAll = 0.f;
#pragma unroll
    for (int i = 0; i < 8; i++) sAll += red[i];
    float inv = 1.f / sAll;
    o[t] = a * inv;
    o[t + 256] = b * inv;
}

// ---------------------------------------------------------------------------
extern "C" void kernel_launch(void* const* d_in, const int* in_sizes, int n_in,
                              void* d_out, int out_size)
{
    const float* key   = (const float*)d_in[0];
    const float* value = (const float*)d_in[1];
    const float* query = (const float*)d_in[2];

    // Inputs 3/4: disambiguate structure vs k_pad_mask by element count.
    const float* structure;
    const void*  kmaskp;
    if (in_sizes[3] == BSZ * LSEQ) {
        kmaskp    = d_in[3];
        structure = (const float*)d_in[4];
    } else {
        structure = (const float*)d_in[3];
        kmaskp    = d_in[4];
    }

    const float* wq  = (const float*)d_in[5];
    const float* bq  = (const float*)d_in[6];
    const float* wk  = (const float*)d_in[7];
    const float* bk  = (const float*)d_in[8];
    const float* wv  = (const float*)d_in[9];
    const float* bv  = (const float*)d_in[10];
    const float* wsk = (const float*)d_in[11];
    // d_in[12] = bsk: softmax-invariant, dropped.
    const float* wsv = (const float*)d_in[13];
    const float* bsv = (const float*)d_in[14];
    const float* wf  = (const float*)d_in[15];
    const float* bf  = (const float*)d_in[16];

    float* out = (float*)d_out;
    float* fin = out + (size_t)BSZ * LSEQ * DM;

    float* scratch = nullptr;
    cudaGetSymbolAddress((void**)&scratch, g_scratch);
    float* qh  = scratch;
    float* kh  = qh + (size_t)BSZ * LSEQ * DM;
    float* vh  = kh + (size_t)BSZ * LSEQ * DM;
    float* ctx = vh + (size_t)BSZ * LSEQ * DM;
    float* sc0 = ctx + (size_t)BSZ * LSEQ * DM;

    detect_mask_kernel<<<1, 256>>>((const unsigned char*)kmaskp, BSZ * LSEQ);

    // M = 8*512 = 4096 rows -> 32 row-tiles of 128; N = 256 -> 2 col-tiles.
    qkv_gemm<<<dim3(2, 32, 3), 256>>>(query, key, value,
                                      wq, wk, wv, bq, bk, bv,
                                      qh, kh, vh);

    cudaFuncSetAttribute(attn_kernel, cudaFuncAttributeMaxDynamicSharedMemorySize, SMEM_BYTES);
    attn_kernel<<<BSZ * (LSEQ / TQ), NTHREADS, SMEM_BYTES>>>(
        qh, kh, vh, structure, kmaskp, wsk, wsv, bsv, ctx, sc0);

    normalize_rows<<<BSZ * LSEQ, 256>>>(sc0, fin);
    gemm128<<<dim3(2, 32), 256>>>(ctx, wf, bf, out, 1.0f);

    // keeps attn_kernel at captured launch index 8 for ncu
    dummy_kernel<<<1, 32>>>();
}

// round 9
// speedup vs baseline: 1.2136x; 1.1145x over previous
#include <cuda_runtime.h>
#include <math.h>

#define BSZ 8
#define LSEQ 512
#define DM 256
#define NH 8
#define DH 32
#define DS 30

#define TQ 8       // q rows per CTA (one warp per head, each warp does all 8)
#define TK 32
#define NKT (LSEQ / TK)
#define NTHREADS 256

// ---- attn dynamic smem layout (float offsets) ----
#define OFF_QS 0                 // [8][8][32]  = 2048
#define OFF_QW 2048              // [8][8][32]  = 2048 (qwsk padded 30->32; reused for ps in epilogue)
#define OFF_ST 4096              // [8][32][31] = 7936 (+32 pad for lane 30/31 overread)
#define SMEM_FLOATS (4096 + 7936 + 32)
#define SMEM_BYTES (SMEM_FLOATS * 4)

// scratch: qh, kh, vh, ctx (each 8*512*256=1M fl) + ktr (1M fl) + scores0 (8*512*512=2M fl)
__device__ float g_scratch[5 * BSZ * LSEQ * DM + BSZ * LSEQ * LSEQ];
__device__ int g_mask_is_byte;

// ---------------------------------------------------------------------------
__global__ void detect_mask_kernel(const unsigned char* __restrict__ m, int nbytes)
{
    __shared__ int any;
    if (threadIdx.x == 0) any = 0;
    __syncthreads();
    int local = 0;
    for (int i = threadIdx.x; i < nbytes; i += blockDim.x)
        if ((i & 3) != 0 && m[i] != 0) local = 1;
    if (local) atomicOr(&any, 1);
    __syncthreads();
    if (threadIdx.x == 0) g_mask_is_byte = any;
}

// ---------------------------------------------------------------------------
// K transpose: ktr[b][n][m] = kh[b*512+m][n]   (so lane=k reads are coalesced)
// ---------------------------------------------------------------------------
__global__ void __launch_bounds__(256) transpose_k(
    const float* __restrict__ kh, float* __restrict__ ktr)
{
    __shared__ float t[32][33];
    const int b = blockIdx.z;
    const int m0 = blockIdx.x * 32, n0 = blockIdx.y * 32;
    const int tx = threadIdx.x, ty = threadIdx.y;

    for (int r = ty; r < 32; r += 8)
        t[r][tx] = kh[(size_t)(b * LSEQ + m0 + r) * DM + n0 + tx];
    __syncthreads();
    for (int r = ty; r < 32; r += 8)
        ktr[(size_t)b * DM * LSEQ + (size_t)(n0 + r) * LSEQ + m0 + tx] = t[tx][r];
}

// ---------------------------------------------------------------------------
// Fast SGEMM: C[M,256] = (A[M,256] @ W[256,256] + bias) * scale
// 128x128 tile, 256 threads, 8x8 microtile, double-buffered smem.
// ---------------------------------------------------------------------------
__device__ __forceinline__ void gemm128_body(
    const float* __restrict__ A, const float* __restrict__ W,
    const float* __restrict__ bias, float* __restrict__ C, float scale,
    int m0, int n0)
{
    __shared__ float As[2][8][128];
    __shared__ float Bs[2][8][128];

    const int tid = threadIdx.x;
    const int am = tid >> 1;
    const int ak = (tid & 1) * 4;
    const int br = tid >> 5;
    const int bc = (tid & 31) * 4;
    const int tx = tid & 15, ty = tid >> 4;

    float4 av = *reinterpret_cast<const float4*>(&A[(size_t)(m0 + am) * 256 + ak]);
    float4 bv = *reinterpret_cast<const float4*>(&W[(size_t)br * 256 + n0 + bc]);

    As[0][ak + 0][am] = av.x; As[0][ak + 1][am] = av.y;
    As[0][ak + 2][am] = av.z; As[0][ak + 3][am] = av.w;
    *reinterpret_cast<float4*>(&Bs[0][br][bc]) = bv;
    __syncthreads();

    float acc[8][8] = {};
    int buf = 0;

    for (int k0 = 0; k0 < 256; k0 += 8) {
        const bool more = (k0 + 8 < 256);
        if (more) {
            av = *reinterpret_cast<const float4*>(&A[(size_t)(m0 + am) * 256 + k0 + 8 + ak]);
            bv = *reinterpret_cast<const float4*>(&W[(size_t)(k0 + 8 + br) * 256 + n0 + bc]);
        }
#pragma unroll
        for (int kk = 0; kk < 8; kk++) {
            float a[8], b[8];
            *reinterpret_cast<float4*>(&a[0]) = *reinterpret_cast<const float4*>(&As[buf][kk][ty * 8]);
            *reinterpret_cast<float4*>(&a[4]) = *reinterpret_cast<const float4*>(&As[buf][kk][ty * 8 + 4]);
            *reinterpret_cast<float4*>(&b[0]) = *reinterpret_cast<const float4*>(&Bs[buf][kk][tx * 8]);
            *reinterpret_cast<float4*>(&b[4]) = *reinterpret_cast<const float4*>(&Bs[buf][kk][tx * 8 + 4]);
#pragma unroll
            for (int i = 0; i < 8; i++)
#pragma unroll
                for (int j = 0; j < 8; j++) acc[i][j] += a[i] * b[j];
        }
        if (more) {
            buf ^= 1;
            As[buf][ak + 0][am] = av.x; As[buf][ak + 1][am] = av.y;
            As[buf][ak + 2][am] = av.z; As[buf][ak + 3][am] = av.w;
            *reinterpret_cast<float4*>(&Bs[buf][br][bc]) = bv;
            __syncthreads();
        }
    }

    float bb[8];
#pragma unroll
    for (int j = 0; j < 8; j++) bb[j] = bias[n0 + tx * 8 + j];
#pragma unroll
    for (int i = 0; i < 8; i++) {
        float4 c0, c1;
        c0.x = (acc[i][0] + bb[0]) * scale; c0.y = (acc[i][1] + bb[1]) * scale;
        c0.z = (acc[i][2] + bb[2]) * scale; c0.w = (acc[i][3] + bb[3]) * scale;
        c1.x = (acc[i][4] + bb[4]) * scale; c1.y = (acc[i][5] + bb[5]) * scale;
        c1.z = (acc[i][6] + bb[6]) * scale; c1.w = (acc[i][7] + bb[7]) * scale;
        float* cp = &C[(size_t)(m0 + ty * 8 + i) * 256 + n0 + tx * 8];
        reinterpret_cast<float4*>(cp)[0] = c0;
        reinterpret_cast<float4*>(cp)[1] = c1;
    }
}

__global__ void __launch_bounds__(256) gemm128(
    const float* __restrict__ A, const float* __restrict__ W,
    const float* __restrict__ bias, float* __restrict__ C, float scale)
{
    gemm128_body(A, W, bias, C, scale, blockIdx.y * 128, blockIdx.x * 128);
}

__global__ void __launch_bounds__(256) qkv_gemm(
    const float* __restrict__ Aq, const float* __restrict__ Ak, const float* __restrict__ Av,
    const float* __restrict__ Wq, const float* __restrict__ Wk, const float* __restrict__ Wv,
    const float* __restrict__ bq, const float* __restrict__ bk, const float* __restrict__ bv,
    float* __restrict__ Cq, float* __restrict__ Ck, float* __restrict__ Cv)
{
    const float *A, *W, *bias; float* C; float scale;
    if (blockIdx.z == 0)      { A = Aq; W = Wq; bias = bq; C = Cq; scale = 0.17677669529663688f; }
    else if (blockIdx.z == 1) { A = Ak; W = Wk; bias = bk; C = Ck; scale = 1.0f; }
    else                      { A = Av; W = Wv; bias = bv; C = Cv; scale = 1.0f; }
    gemm128_body(A, W, bias, C, scale, blockIdx.y * 128, blockIdx.x * 128);
}

// ---------------------------------------------------------------------------
// Fused attention, fixed-max softmax. 256 threads, warp = head, 8 q-rows/CTA,
// 2 CTAs/SM. K from ktr (coalesced global), V direct from vh (coalesced
// global, next-k prefetch). ST in smem; QW reused for ps in the epilogue.
// ---------------------------------------------------------------------------
__global__ void __launch_bounds__(NTHREADS, 2) attn_kernel(
    const float* __restrict__ qh, const float* __restrict__ ktr, const float* __restrict__ vh,
    const float* __restrict__ st_g, const void* __restrict__ kmask_raw,
    const float* __restrict__ wsk, const float* __restrict__ wsv, const float* __restrict__ bsv,
    float* __restrict__ ctx, float* __restrict__ scores0)
{
    extern __shared__ float sm[];
    float* QS = sm + OFF_QS;
    float* QW = sm + OFF_QW;
    float* ST = sm + OFF_ST;

    const int tid = threadIdx.x;
    const int h = tid >> 5, lane = tid & 31;     // warp = head
    const int b = blockIdx.x >> 6;
    const int q0 = (blockIdx.x & 63) * TQ;
    const int mask_is_byte = g_mask_is_byte;
    const unsigned char* km8 = (const unsigned char*)kmask_raw;
    const int* km32 = (const int*)kmask_raw;

    // staging identity: warp h stages q-row h (8 warps, 8 rows)
    const float* st_qrow = st_g + (((size_t)b * LSEQ + q0 + h) * LSEQ) * DS;
    float* st_dst = &ST[h * 32 * 31];
    const int ek0 = (lane * 2) / DS;
    const int es0 = (lane * 2) % DS;

    const float* ktb = ktr + (size_t)b * DM * LSEQ + (size_t)(h * 32) * LSEQ;
    const float* vb  = vh + ((size_t)b * LSEQ) * DM + h * 32 + lane;

    // ---- load Q tile [8][256] -> QS[h][q][32]; wsk -> ST temp; zero QW ----
    {
        const float4* qg4 = reinterpret_cast<const float4*>(qh + ((size_t)b * LSEQ + q0) * DM);
        for (int f = tid; f < TQ * DM / 4; f += NTHREADS) {
            int q = f >> 6, c4 = f & 63;
            float4 v = qg4[f];
            int hh = c4 >> 3, d = (c4 & 7) * 4;
            float* dst = &QS[(hh * TQ + q) * 32 + d];
            dst[0] = v.x; dst[1] = v.y; dst[2] = v.z; dst[3] = v.w;
        }
    }
    for (int i = tid; i < DS * DH; i += NTHREADS) ST[i] = wsk[i];
    for (int i = tid; i < NH * TQ * 32; i += NTHREADS) QW[i] = 0.f;
    __syncthreads();

    // qwsk[h,q,s] = sum_d QS[h,q,d] * wsk[s,d]
    for (int i = tid; i < NH * TQ * DS; i += NTHREADS) {
        int hh = i / (TQ * DS);
        int r = i - hh * (TQ * DS);
        int q = r / DS;
        int s = r - q * DS;
        const float* qp = &QS[(hh * TQ + q) * 32];
        const float* wp = &ST[s * 32];
        float a = 0.f;
#pragma unroll
        for (int d = 0; d < 32; d++) a += qp[d] * wp[d];
        QW[(hh * TQ + q) * 32 + s] = a;
    }
    __syncthreads();

    // ---- initial ST staging (coalesced LDG -> (k,s) walk STS) ----
    float2 pre[15];
    {
        const float2* src = reinterpret_cast<const float2*>(st_qrow);
#pragma unroll
        for (int i = 0; i < 15; i++) pre[i] = src[i * 32 + lane];
    }
    {
        int kk = ek0, ss = es0;
#pragma unroll
        for (int i = 0; i < 15; i++) {
            st_dst[kk * 31 + ss] = pre[i].x;
            int k2 = kk, s2 = ss + 1;
            if (s2 == DS) { s2 = 0; k2++; }
            st_dst[k2 * 31 + s2] = pre[i].y;
            ss += 4; kk += 2;                 // advance e by 64 (64 = 2*30 + 4)
            if (ss >= DS) { ss -= DS; kk++; }
        }
    }
    __syncthreads();

    float acc[TQ], ps[TQ], lsum[TQ];
#pragma unroll
    for (int q = 0; q < TQ; q++) { acc[q] = 0.f; ps[q] = 0.f; lsum[q] = 0.f; }

    for (int kt = 0; kt < NKT; kt++) {
        const int k0 = kt * TK;

        // prefetch next struct slice into registers (coalesced)
        if (kt + 1 < NKT) {
            const float2* src = reinterpret_cast<const float2*>(st_qrow + (size_t)(k0 + TK) * DS);
#pragma unroll
            for (int i = 0; i < 15; i++) pre[i] = src[i * 32 + lane];
        }

        const int midx = b * LSEQ + k0 + lane;
        const bool masked = mask_is_byte ? (km8[midx] != 0) : (km32[midx] != 0);

        // K column for this lane's k: ktr[b][h*32+d][k0+lane], coalesced per d
        float kreg[32];
        {
            const float* kp = ktb + k0 + lane;
#pragma unroll
            for (int d = 0; d < 32; d++) kreg[d] = kp[(size_t)d * LSEQ];
        }

        float preg[TQ];
#pragma unroll
        for (int q = 0; q < TQ; q++) {
            const float4* qv = reinterpret_cast<const float4*>(&QS[(h * TQ + q) * 32]);
            float s = 0.f;
#pragma unroll
            for (int d4 = 0; d4 < 8; d4++) {
                float4 qd = qv[d4];
                s += qd.x * kreg[d4 * 4] + qd.y * kreg[d4 * 4 + 1]
                   + qd.z * kreg[d4 * 4 + 2] + qd.w * kreg[d4 * 4 + 3];
            }
            const float4* qwv = reinterpret_cast<const float4*>(&QW[(h * TQ + q) * 32]);
            const float* stp = &ST[(q * 32 + lane) * 31];
#pragma unroll
            for (int s4 = 0; s4 < 7; s4++) {
                float4 ww = qwv[s4];
                s += ww.x * stp[s4 * 4] + ww.y * stp[s4 * 4 + 1]
                   + ww.z * stp[s4 * 4 + 2] + ww.w * stp[s4 * 4 + 3];
            }
            s += QW[(h * TQ + q) * 32 + 28] * stp[28] + QW[(h * TQ + q) * 32 + 29] * stp[29];
            if (masked) s = -1e30f;

            float p = __expf(s);
            preg[q] = p;
            lsum[q] += p;
            if (h == 0)
                scores0[((size_t)(b * LSEQ + q0 + q)) * LSEQ + k0 + lane] = p;
        }

        // ---- accumulate: acc[q] += p*v[d=lane] (global V), ps[q] += p*ST[s=lane] ----
        {
            const float* vk = vb + (size_t)k0 * DM;
            float vv = vk[0];
#pragma unroll 4
            for (int k = 0; k < TK; k++) {
                float vnext = (k + 1 < TK) ? vk[(size_t)(k + 1) * DM] : 0.f;
                const float* stk = &ST[k * 31 + lane];
#pragma unroll
                for (int q = 0; q < TQ; q++) {
                    float p = __shfl_sync(0xffffffffu, preg[q], k);
                    acc[q] += p * vv;
                    ps[q]  += p * stk[q * 992];
                }
                vv = vnext;
            }
        }

        __syncthreads();
        if (kt + 1 < NKT) {
            int kk = ek0, ss = es0;
#pragma unroll
            for (int i = 0; i < 15; i++) {
                st_dst[kk * 31 + ss] = pre[i].x;
                int k2 = kk, s2 = ss + 1;
                if (s2 == DS) { s2 = 0; k2++; }
                st_dst[k2 * 31 + s2] = pre[i].y;
                ss += 4; kk += 2;
                if (ss >= DS) { ss -= DS; kk++; }
            }
            __syncthreads();
        }
    }

    // ---- final row-sum reduction ----
#pragma unroll
    for (int q = 0; q < TQ; q++) {
        float l = lsum[q];
#pragma unroll
        for (int off = 16; off; off >>= 1)
            l += __shfl_xor_sync(0xffffffffu, l, off);
        lsum[q] = l;
    }

    // ---- epilogue: ctx = (acc + ps@wsv)/l + bsv ----
    __syncthreads();
    // wsv -> QS region (dead), ps -> QW region (dead)
    for (int i = tid; i < DS * DH; i += NTHREADS) QS[i] = wsv[i];
#pragma unroll
    for (int q = 0; q < TQ; q++)
        QW[(h * TQ + q) * 32 + lane] = ps[q];   // lanes 30/31 hold zeros (pad reads)
    __syncthreads();

    const float bsvv = bsv[lane];
#pragma unroll
    for (int q = 0; q < TQ; q++) {
        float inv = 1.f / lsum[q];
        float c = acc[q];
        const float* pr = &QW[(h * TQ + q) * 32];
#pragma unroll
        for (int s = 0; s < DS; s++) c += pr[s] * QS[s * 32 + lane];
        ctx[((size_t)(b * LSEQ + q0 + q)) * DM + h * 32 + lane] = c * inv + bsvv;
    }
}

// ---------------------------------------------------------------------------
// Normalize rows of unnormalized p (fin_attn): out = p / sum(p).
// ---------------------------------------------------------------------------
__global__ void __launch_bounds__(256) normalize_rows(
    const float* __restrict__ P, float* __restrict__ O)
{
    const int row = blockIdx.x;
    const float* s = P + (size_t)row * LSEQ;
    float* o = O + (size_t)row * LSEQ;
    const int t = threadIdx.x;

    float a = s[t], b = s[t + 256];
    float sum = a + b;
    __shared__ float red[8];
#pragma unroll
    for (int off = 16; off; off >>= 1) sum += __shfl_xor_sync(0xffffffffu, sum, off);
    if ((t & 31) == 0) red[t >> 5] = sum;
    __syncthreads();
    float sAll = 0.f;
#pragma unroll
    for (int i = 0; i < 8; i++) sAll += red[i];
    float inv = 1.f / sAll;
    o[t] = a * inv;
    o[t + 256] = b * inv;
}

// ---------------------------------------------------------------------------
extern "C" void kernel_launch(void* const* d_in, const int* in_sizes, int n_in,
                              void* d_out, int out_size)
{
    const float* key   = (const float*)d_in[0];
    const float* value = (const float*)d_in[1];
    const float* query = (const float*)d_in[2];

    const float* structure;
    const void*  kmaskp;
    if (in_sizes[3] == BSZ * LSEQ) {
        kmaskp    = d_in[3];
        structure = (const float*)d_in[4];
    } else {
        structure = (const float*)d_in[3];
        kmaskp    = d_in[4];
    }

    const float* wq  = (const float*)d_in[5];
    const float* bq  = (const float*)d_in[6];
    const float* wk  = (const float*)d_in[7];
    const float* bk  = (const float*)d_in[8];
    const float* wv  = (const float*)d_in[9];
    const float* bv  = (const float*)d_in[10];
    const float* wsk = (const float*)d_in[11];
    // d_in[12] = bsk: softmax-invariant, dropped.
    const float* wsv = (const float*)d_in[13];
    const float* bsv = (const float*)d_in[14];
    const float* wf  = (const float*)d_in[15];
    const float* bf  = (const float*)d_in[16];

    float* out = (float*)d_out;
    float* fin = out + (size_t)BSZ * LSEQ * DM;

    float* scratch = nullptr;
    cudaGetSymbolAddress((void**)&scratch, g_scratch);
    float* qh  = scratch;
    float* kh  = qh + (size_t)BSZ * LSEQ * DM;
    float* vh  = kh + (size_t)BSZ * LSEQ * DM;
    float* ctx = vh + (size_t)BSZ * LSEQ * DM;
    float* ktr = ctx + (size_t)BSZ * LSEQ * DM;
    float* sc0 = ktr + (size_t)BSZ * LSEQ * DM;

    detect_mask_kernel<<<1, 256>>>((const unsigned char*)kmaskp, BSZ * LSEQ);

    qkv_gemm<<<dim3(2, 32, 3), 256>>>(query, key, value,
                                      wq, wk, wv, bq, bk, bv,
                                      qh, kh, vh);

    transpose_k<<<dim3(16, 8, 8), dim3(32, 8)>>>(kh, ktr);

    cudaFuncSetAttribute(attn_kernel, cudaFuncAttributeMaxDynamicSharedMemorySize, SMEM_BYTES);
    attn_kernel<<<BSZ * (LSEQ / TQ), NTHREADS, SMEM_BYTES>>>(
        qh, ktr, vh, structure, kmaskp, wsk, wsv, bsv, ctx, sc0);

    normalize_rows<<<BSZ * LSEQ, 256>>>(sc0, fin);
    gemm128<<<dim3(2, 32), 256>>>(ctx, wf, bf, out, 1.0f);
}